// round 1
// baseline (speedup 1.0000x reference)
#include <cuda_runtime.h>
#include <math.h>
#include <stdint.h>

// ---------------- problem constants ----------------
#define Bb      2
#define Ss      2048
#define HIDc    2048
#define NHh     16
#define DNOPE   128
#define DROPE   64
#define DVv     128
#define DQK     192
#define KVRANK  512
#define NTOK    (Bb*Ss)            // 4096
// SCALE = 1/sqrt(192)
#define ATT_SCALE 0.072168783648703220563f
#define LN_EPS 1e-5f

// ---------------- scratch (static device globals; no allocation) ----------------
__device__ float g_q    [(size_t)NTOK * NHh * DQK];          // [tok][h*192+d]  (rope applied in place)
__device__ float g_kva  [(size_t)NTOK * (KVRANK + DROPE)];   // [tok][576]
__device__ float g_kvlat[(size_t)NTOK * KVRANK];             // [tok][512] post-LN
__device__ float g_krope[(size_t)NTOK * DROPE];              // [tok][64]
__device__ float g_kv   [(size_t)NTOK * NHh * (DNOPE+DVv)];  // [tok][h*256 + d]  (0:128 k_nope, 128:256 v)
__device__ float g_attn [(size_t)NTOK * NHh * DVv];          // [tok][h*128+d]

// ---------------- generic fp32 SGEMM: C[M,N] = A[M,K] @ B[K,N] ----------------
// BM=128 BN=128 BK=16, 256 threads, 8x8 per thread. M%128==0, K%16==0, N%4==0 (guarded).
__global__ __launch_bounds__(256) void sgemm_kernel(
    const float* __restrict__ A, const float* __restrict__ B, float* __restrict__ C,
    int M, int N, int K)
{
    __shared__ float As[16][132];   // [k][m], padded
    __shared__ float Bs[16][128];   // [k][n]

    const int tid = threadIdx.x;
    const int tx  = tid & 15;       // 0..15 -> n
    const int ty  = tid >> 4;       // 0..15 -> m
    const int bm  = blockIdx.y * 128;
    const int bn  = blockIdx.x * 128;

    float acc[8][8];
    #pragma unroll
    for (int i = 0; i < 8; i++)
        #pragma unroll
        for (int j = 0; j < 8; j++) acc[i][j] = 0.f;

    for (int k0 = 0; k0 < K; k0 += 16) {
        // load A tile (128x16): 512 float4, 2 per thread
        #pragma unroll
        for (int i = 0; i < 2; i++) {
            int v   = tid + i * 256;
            int row = v >> 2;            // 0..127
            int kc  = (v & 3) * 4;       // 0,4,8,12
            float4 a = *(const float4*)&A[(size_t)(bm + row) * K + k0 + kc];
            As[kc + 0][row] = a.x;
            As[kc + 1][row] = a.y;
            As[kc + 2][row] = a.z;
            As[kc + 3][row] = a.w;
        }
        // load B tile (16x128): 512 float4, 2 per thread (N-guarded)
        #pragma unroll
        for (int i = 0; i < 2; i++) {
            int v    = tid + i * 256;
            int kr   = v >> 5;           // 0..15
            int col  = (v & 31) * 4;     // 0..124
            int gcol = bn + col;
            float4 b = (gcol < N) ? *(const float4*)&B[(size_t)(k0 + kr) * N + gcol]
                                  : make_float4(0.f, 0.f, 0.f, 0.f);
            *(float4*)&Bs[kr][col] = b;
        }
        __syncthreads();
        #pragma unroll
        for (int k = 0; k < 16; k++) {
            float4 a0 = *(const float4*)&As[k][ty * 8];
            float4 a1 = *(const float4*)&As[k][ty * 8 + 4];
            float4 b0 = *(const float4*)&Bs[k][tx * 8];
            float4 b1 = *(const float4*)&Bs[k][tx * 8 + 4];
            float ar[8] = {a0.x, a0.y, a0.z, a0.w, a1.x, a1.y, a1.z, a1.w};
            float br[8] = {b0.x, b0.y, b0.z, b0.w, b1.x, b1.y, b1.z, b1.w};
            #pragma unroll
            for (int i = 0; i < 8; i++)
                #pragma unroll
                for (int j = 0; j < 8; j++)
                    acc[i][j] = fmaf(ar[i], br[j], acc[i][j]);
        }
        __syncthreads();
    }

    #pragma unroll
    for (int i = 0; i < 8; i++) {
        int grow = bm + ty * 8 + i;
        #pragma unroll
        for (int j = 0; j < 8; j += 4) {
            int gcol = bn + tx * 8 + j;
            if (gcol < N) {
                float4 v = make_float4(acc[i][j], acc[i][j+1], acc[i][j+2], acc[i][j+3]);
                *(float4*)&C[(size_t)grow * N + gcol] = v;
            }
        }
    }
}

// ---------------- prep: rope(q), rope(k_rope), layernorm(kv_lat) ----------------
// one block (128 threads) per token
__global__ __launch_bounds__(128) void prep_kernel(
    const float* __restrict__ fc,    // [S,32,2] cos/sin
    const float* __restrict__ lnw, const float* __restrict__ lnb)
{
    const int tok = blockIdx.x;          // 0..NTOK-1
    const int s   = tok & (Ss - 1);      // position (Ss power of 2)
    const int tid = threadIdx.x;

    // ---- layernorm over g_kva[tok][0:512] -> g_kvlat ----
    const float* x = &g_kva[(size_t)tok * (KVRANK + DROPE)];
    float local[4];
    float sum = 0.f;
    #pragma unroll
    for (int i = 0; i < 4; i++) { local[i] = x[tid + i * 128]; sum += local[i]; }
    __shared__ float red[4];
    #pragma unroll
    for (int o = 16; o > 0; o >>= 1) sum += __shfl_xor_sync(0xffffffffu, sum, o);
    if ((tid & 31) == 0) red[tid >> 5] = sum;
    __syncthreads();
    const float mean = (red[0] + red[1] + red[2] + red[3]) * (1.f / 512.f);
    float vs = 0.f;
    #pragma unroll
    for (int i = 0; i < 4; i++) { float d = local[i] - mean; vs = fmaf(d, d, vs); }
    #pragma unroll
    for (int o = 16; o > 0; o >>= 1) vs += __shfl_xor_sync(0xffffffffu, vs, o);
    __syncthreads();                      // all reads of red[] for mean are done
    if ((tid & 31) == 0) red[tid >> 5] = vs;
    __syncthreads();
    const float var  = (red[0] + red[1] + red[2] + red[3]) * (1.f / 512.f);
    const float rstd = rsqrtf(var + LN_EPS);
    #pragma unroll
    for (int i = 0; i < 4; i++) {
        int c = tid + i * 128;
        g_kvlat[(size_t)tok * KVRANK + c] = (local[i] - mean) * rstd * lnw[c] + lnb[c];
    }

    const float* fcs = &fc[(size_t)s * 64];

    // ---- rope on k_rope (32 pairs) -> g_krope ----
    if (tid < 32) {
        float c  = fcs[tid * 2 + 0];
        float sn = fcs[tid * 2 + 1];
        float x0 = x[KVRANK + 2 * tid];
        float x1 = x[KVRANK + 2 * tid + 1];
        g_krope[(size_t)tok * DROPE + 2 * tid]     = x0 * c - x1 * sn;
        g_krope[(size_t)tok * DROPE + 2 * tid + 1] = x0 * sn + x1 * c;
    }

    // ---- rope on q (16 heads x 32 pairs = 512 pairs), in place ----
    #pragma unroll
    for (int i = 0; i < 4; i++) {
        int p  = tid + i * 128;     // 0..511
        int h  = p >> 5;
        int pi = p & 31;
        float c  = fcs[pi * 2 + 0];
        float sn = fcs[pi * 2 + 1];
        size_t base = (size_t)tok * (NHh * DQK) + h * DQK + DNOPE + 2 * pi;
        float x0 = g_q[base], x1 = g_q[base + 1];
        g_q[base]     = x0 * c - x1 * sn;
        g_q[base + 1] = x0 * sn + x1 * c;
    }
}

// ---------------- flash attention: per (b,h), 64q x 64k tiles ----------------
// grid: (Ss/64, Bb*NHh), 256 threads. Online softmax. k = [kv_nope | krope], v from g_kv.
#define QPAD 193
__global__ __launch_bounds__(256) void flash_kernel()
{
    const int qt  = (int)gridDim.x - 1 - (int)blockIdx.x;   // big tiles first
    const int bh  = blockIdx.y;
    const int b   = bh >> 4;
    const int h   = bh & 15;
    const int tid = threadIdx.x;
    const int tx  = tid & 15;     // key-col group / value d group
    const int ty  = tid >> 4;     // query-row group

    extern __shared__ float sm[];
    float* Qs = sm;                       // [64][193]
    float* Ks = sm + 64 * QPAD;           // [64][193]
    float* Vs = sm + 2 * 64 * QPAD;       // [64][128]
    float* Ps = Vs + 64 * 128;            // [64][65]

    const int q0 = qt * 64;
    const size_t tok0 = (size_t)b * Ss;

    // load Q tile (rope already applied)
    for (int idx = tid; idx < 64 * 48; idx += 256) {
        int row = idx / 48, d4 = idx % 48;
        float4 v = *(const float4*)&g_q[(tok0 + q0 + row) * (NHh * DQK) + h * DQK + d4 * 4];
        Qs[row * QPAD + d4 * 4 + 0] = v.x;
        Qs[row * QPAD + d4 * 4 + 1] = v.y;
        Qs[row * QPAD + d4 * 4 + 2] = v.z;
        Qs[row * QPAD + d4 * 4 + 3] = v.w;
    }

    float o[4][8];
    #pragma unroll
    for (int r = 0; r < 4; r++)
        #pragma unroll
        for (int k = 0; k < 8; k++) o[r][k] = 0.f;
    float m[4] = {-1e30f, -1e30f, -1e30f, -1e30f};
    float l[4] = {0.f, 0.f, 0.f, 0.f};

    for (int jt = 0; jt <= qt; jt++) {
        const int j0 = jt * 64;
        // (a) load K tile: nope from g_kv, rope from g_krope
        for (int idx = tid; idx < 64 * 48; idx += 256) {
            int row = idx / 48, d4 = idx % 48;
            float4 v;
            if (d4 < 32)
                v = *(const float4*)&g_kv[(tok0 + j0 + row) * (NHh * 256) + h * 256 + d4 * 4];
            else
                v = *(const float4*)&g_krope[(tok0 + j0 + row) * DROPE + (d4 - 32) * 4];
            Ks[row * QPAD + d4 * 4 + 0] = v.x;
            Ks[row * QPAD + d4 * 4 + 1] = v.y;
            Ks[row * QPAD + d4 * 4 + 2] = v.z;
            Ks[row * QPAD + d4 * 4 + 3] = v.w;
        }
        __syncthreads();   // (b)

        // (c) S = Q K^T  (4x4 per thread)
        float sacc[4][4];
        #pragma unroll
        for (int r = 0; r < 4; r++)
            #pragma unroll
            for (int c = 0; c < 4; c++) sacc[r][c] = 0.f;
        #pragma unroll 4
        for (int d = 0; d < DQK; d++) {
            float qr[4], kr[4];
            #pragma unroll
            for (int r = 0; r < 4; r++) qr[r] = Qs[(ty * 4 + r) * QPAD + d];
            #pragma unroll
            for (int c = 0; c < 4; c++) kr[c] = Ks[(tx * 4 + c) * QPAD + d];
            #pragma unroll
            for (int r = 0; r < 4; r++)
                #pragma unroll
                for (int c = 0; c < 4; c++)
                    sacc[r][c] = fmaf(qr[r], kr[c], sacc[r][c]);
        }

        // (d) online softmax + write P
        const bool diag = (jt == qt);
        #pragma unroll
        for (int r = 0; r < 4; r++) {
            const int gi = ty * 4 + r;
            float mx = -1e30f;
            #pragma unroll
            for (int c = 0; c < 4; c++) {
                float sv = sacc[r][c] * ATT_SCALE;
                if (diag && (tx * 4 + c) > gi) sv = -1e30f;
                sacc[r][c] = sv;
                mx = fmaxf(mx, sv);
            }
            #pragma unroll
            for (int o2 = 8; o2 > 0; o2 >>= 1)
                mx = fmaxf(mx, __shfl_xor_sync(0xffffffffu, mx, o2));
            const float mn = fmaxf(m[r], mx);
            const float alpha = __expf(m[r] - mn);
            float rs = 0.f;
            #pragma unroll
            for (int c = 0; c < 4; c++) {
                float p = __expf(sacc[r][c] - mn);
                rs += p;
                Ps[gi * 65 + tx * 4 + c] = p;
            }
            #pragma unroll
            for (int o2 = 8; o2 > 0; o2 >>= 1)
                rs += __shfl_xor_sync(0xffffffffu, rs, o2);
            l[r] = l[r] * alpha + rs;
            m[r] = mn;
            #pragma unroll
            for (int k = 0; k < 8; k++) o[r][k] *= alpha;
        }
        __syncthreads();   // (e)

        // (f) load V tile
        for (int idx = tid; idx < 64 * 32; idx += 256) {
            int row = idx >> 5, d4 = idx & 31;
            *(float4*)&Vs[row * 128 + d4 * 4] =
                *(const float4*)&g_kv[(tok0 + j0 + row) * (NHh * 256) + h * 256 + 128 + d4 * 4];
        }
        __syncthreads();   // (g)

        // (h) O += P V   (rows ty*4+r, cols tx*8..tx*8+7)
        #pragma unroll 2
        for (int j = 0; j < 64; j++) {
            float pr[4];
            #pragma unroll
            for (int r = 0; r < 4; r++) pr[r] = Ps[(ty * 4 + r) * 65 + j];
            float4 v0 = *(const float4*)&Vs[j * 128 + tx * 8];
            float4 v1 = *(const float4*)&Vs[j * 128 + tx * 8 + 4];
            float vr[8] = {v0.x, v0.y, v0.z, v0.w, v1.x, v1.y, v1.z, v1.w};
            #pragma unroll
            for (int r = 0; r < 4; r++)
                #pragma unroll
                for (int k = 0; k < 8; k++)
                    o[r][k] = fmaf(pr[r], vr[k], o[r][k]);
        }
        __syncthreads();   // protect Ks/Ps/Vs for next iteration's writes
    }

    // write O/l -> g_attn [tok][h*128 + d]
    #pragma unroll
    for (int r = 0; r < 4; r++) {
        const float inv = 1.f / l[r];
        const int row = q0 + ty * 4 + r;
        size_t base = (tok0 + row) * (NHh * DVv) + h * DVv + tx * 8;
        float4 w0 = make_float4(o[r][0]*inv, o[r][1]*inv, o[r][2]*inv, o[r][3]*inv);
        float4 w1 = make_float4(o[r][4]*inv, o[r][5]*inv, o[r][6]*inv, o[r][7]*inv);
        *(float4*)&g_attn[base]     = w0;
        *(float4*)&g_attn[base + 4] = w1;
    }
}

// ---------------- launch ----------------
extern "C" void kernel_launch(void* const* d_in, const int* in_sizes, int n_in,
                              void* d_out, int out_size)
{
    const float* hs   = (const float*)d_in[0];  // [B,S,HID]
    const float* fc   = (const float*)d_in[1];  // [S,32,2]
    // d_in[2] attention_mask: pure causal, applied analytically
    const float* Wq   = (const float*)d_in[3];  // [2048,3072]
    const float* Wkva = (const float*)d_in[4];  // [2048,576]
    const float* lnw  = (const float*)d_in[5];  // [512]
    const float* lnb  = (const float*)d_in[6];  // [512]
    const float* Wkvb = (const float*)d_in[7];  // [512,4096]
    const float* Wo   = (const float*)d_in[8];  // [2048,2048]
    float* out = (float*)d_out;

    static float *p_q = nullptr, *p_kva = nullptr, *p_kvlat = nullptr,
                 *p_kv = nullptr, *p_attn = nullptr;
    static int smem_flash = 0;
    if (p_q == nullptr) {
        // first call is the (uncaptured) correctness run; these are plain
        // lookups/attribute sets, no allocation, and results are cached.
        cudaGetSymbolAddress((void**)&p_q,     g_q);
        cudaGetSymbolAddress((void**)&p_kva,   g_kva);
        cudaGetSymbolAddress((void**)&p_kvlat, g_kvlat);
        cudaGetSymbolAddress((void**)&p_kv,    g_kv);
        cudaGetSymbolAddress((void**)&p_attn,  g_attn);
        smem_flash = (2 * 64 * QPAD + 64 * 128 + 64 * 65) * (int)sizeof(float);
        cudaFuncSetAttribute(flash_kernel,
                             cudaFuncAttributeMaxDynamicSharedMemorySize, smem_flash);
    }

    // 1) q = hidden @ Wq                     [4096, 3072]
    sgemm_kernel<<<dim3(3072 / 128, NTOK / 128), 256>>>(hs, Wq, p_q, NTOK, 3072, HIDc);
    // 2) kv_a = hidden @ Wkv_a               [4096, 576]
    sgemm_kernel<<<dim3((576 + 127) / 128, NTOK / 128), 256>>>(hs, Wkva, p_kva, NTOK, 576, HIDc);
    // 3) rope(q), rope(k_rope), layernorm(kv_lat)
    prep_kernel<<<NTOK, 128>>>(fc, lnw, lnb);
    // 4) kv = kv_lat @ Wkv_b                 [4096, 4096]
    sgemm_kernel<<<dim3(4096 / 128, NTOK / 128), 256>>>(p_kvlat, Wkvb, p_kv, NTOK, 4096, KVRANK);
    // 5) flash attention -> g_attn           [4096, 2048]
    flash_kernel<<<dim3(Ss / 64, Bb * NHh), 256, smem_flash>>>();
    // 6) out = attn @ Wo                     [4096, 2048]
    sgemm_kernel<<<dim3(2048 / 128, NTOK / 128), 256>>>(p_attn, Wo, out, NTOK, 2048, HIDc);
}

// round 3
// speedup vs baseline: 1.4549x; 1.4549x over previous
#include <cuda_runtime.h>
#include <cuda_bf16.h>
#include <math.h>
#include <stdint.h>

// ---------------- problem constants ----------------
#define Bb      2
#define Ss      2048
#define HIDc    2048
#define NHh     16
#define DNOPE   128
#define DROPE   64
#define DVv     128
#define DQK     192
#define KVRANK  512
#define NTOK    (Bb*Ss)            // 4096
#define KVA_PAD 640                // 576 padded to multiple of 128
#define ATT_SCALE 0.072168783648703220563f
#define LN_EPS 1e-5f

// ---------------- scratch (static device globals; no allocation) ----------------
__device__ float g_q    [(size_t)NTOK * NHh * DQK];
__device__ float g_kva  [(size_t)NTOK * KVA_PAD];
__device__ float g_krope[(size_t)NTOK * DROPE];
__device__ float g_kv   [(size_t)NTOK * NHh * (DNOPE+DVv)];
// bf16 split operands
__device__ __nv_bfloat16 g_hs_h [(size_t)NTOK * HIDc];
__device__ __nv_bfloat16 g_hs_l [(size_t)NTOK * HIDc];
__device__ __nv_bfloat16 g_WqT_h [(size_t)3072 * HIDc];
__device__ __nv_bfloat16 g_WqT_l [(size_t)3072 * HIDc];
__device__ __nv_bfloat16 g_WkvaT_h[(size_t)KVA_PAD * HIDc];
__device__ __nv_bfloat16 g_WkvaT_l[(size_t)KVA_PAD * HIDc];
__device__ __nv_bfloat16 g_WkvbT_h[(size_t)4096 * KVRANK];
__device__ __nv_bfloat16 g_WkvbT_l[(size_t)4096 * KVRANK];
__device__ __nv_bfloat16 g_WoT_h [(size_t)HIDc * HIDc];
__device__ __nv_bfloat16 g_WoT_l [(size_t)HIDc * HIDc];
__device__ __nv_bfloat16 g_kvlat_h[(size_t)NTOK * KVRANK];
__device__ __nv_bfloat16 g_kvlat_l[(size_t)NTOK * KVRANK];
__device__ __nv_bfloat16 g_attn_h[(size_t)NTOK * NHh * DVv];
__device__ __nv_bfloat16 g_attn_l[(size_t)NTOK * NHh * DVv];

// ================= helpers =================
__device__ __forceinline__ uint32_t smem_u32(const void* p) {
    uint32_t a;
    asm("{ .reg .u64 t; cvta.to.shared.u64 t, %1; cvt.u32.u64 %0, t; }" : "=r"(a) : "l"(p));
    return a;
}
__device__ __forceinline__ void ldsm4(uint32_t* r, uint32_t addr) {
    asm volatile("ldmatrix.sync.aligned.m8n8.x4.shared.b16 {%0,%1,%2,%3}, [%4];"
        : "=r"(r[0]), "=r"(r[1]), "=r"(r[2]), "=r"(r[3]) : "r"(addr));
}
__device__ __forceinline__ void mma16816(float* d, const uint32_t* a, const uint32_t* b) {
    asm volatile("mma.sync.aligned.m16n8k16.row.col.f32.bf16.bf16.f32 "
        "{%0,%1,%2,%3}, {%4,%5,%6,%7}, {%8,%9}, {%0,%1,%2,%3};"
        : "+f"(d[0]), "+f"(d[1]), "+f"(d[2]), "+f"(d[3])
        : "r"(a[0]), "r"(a[1]), "r"(a[2]), "r"(a[3]), "r"(b[0]), "r"(b[1]));
}

// ============ mma.sync bf16-split GEMM: C[M,N] = A[M,K] @ B^T[N,K] ============
// (Ah,Al) row-major [M,K]; (Bh,Bl) row-major [N,K]. M,N mult of 128; K mult of 32.
#define BKp     40                         // padded bf16 row stride (80B, 16B-mult)
#define TILE_B  (128 * BKp * 2)            // 10240 bytes per operand tile
#define STAGE_B (4 * TILE_B)               // 40960
#define GS_SMEM (2 * STAGE_B)              // 81920

__global__ __launch_bounds__(256) void mma_gemm(
    const __nv_bfloat16* __restrict__ Ah, const __nv_bfloat16* __restrict__ Al,
    const __nv_bfloat16* __restrict__ Bh, const __nv_bfloat16* __restrict__ Bl,
    float* __restrict__ C, int M, int N, int K)
{
    extern __shared__ char dsm[];
    const uint32_t sbase = smem_u32(dsm);
    const int tid = threadIdx.x, wid = tid >> 5, lane = tid & 31;
    const int wm = wid >> 2, wn = wid & 3;           // 2 x 4 warp grid
    const int bm = blockIdx.y * 128, bn = blockIdx.x * 128;

    const __nv_bfloat16* srcs[4] = {
        Ah + (size_t)bm * K, Al + (size_t)bm * K,
        Bh + (size_t)bn * K, Bl + (size_t)bn * K };

    auto load_chunk = [&](int c, int s) {
        #pragma unroll
        for (int t = 0; t < 4; t++) {
            const __nv_bfloat16* src = srcs[t] + c * 32;
            uint32_t tb = sbase + s * STAGE_B + t * TILE_B;
            #pragma unroll
            for (int i = 0; i < 2; i++) {
                int u = tid + i * 256;
                int row = u >> 2, c8 = u & 3;
                const void* g = src + (size_t)row * K + c8 * 8;
                uint32_t d = tb + (uint32_t)(row * BKp + c8 * 8) * 2;
                asm volatile("cp.async.cg.shared.global [%0], [%1], 16;" :: "r"(d), "l"(g));
            }
        }
        asm volatile("cp.async.commit_group;" ::: "memory");
    };

    float acc[16][4];
    #pragma unroll
    for (int i = 0; i < 16; i++)
        #pragma unroll
        for (int j = 0; j < 4; j++) acc[i][j] = 0.f;

    const int nchunk = K >> 5;
    load_chunk(0, 0);

    for (int c = 0; c < nchunk; c++) {
        const int s = c & 1;
        if (c + 1 < nchunk) {
            load_chunk(c + 1, s ^ 1);
            asm volatile("cp.async.wait_group 1;" ::: "memory");
        } else {
            asm volatile("cp.async.wait_group 0;" ::: "memory");
        }
        __syncthreads();
        const uint32_t stg = sbase + s * STAGE_B;
        #pragma unroll
        for (int ks = 0; ks < 2; ks++) {
            const int k0 = ks * 16;
            #pragma unroll
            for (int t = 0; t < 3; t++) {                 // (AhBh, AhBl, AlBh)
                const int at = (t == 2) ? 1 : 0;
                const int bt = (t == 1) ? 3 : 2;
                const uint32_t abase = stg + at * TILE_B;
                const uint32_t bbase = stg + bt * TILE_B;
                uint32_t af[4][4], bf[8];
                #pragma unroll
                for (int mi = 0; mi < 4; mi++) {
                    uint32_t addr = abase +
                        (uint32_t)((wm * 64 + mi * 16 + (lane & 15)) * BKp + k0 + ((lane >> 4) << 3)) * 2;
                    ldsm4(af[mi], addr);
                }
                #pragma unroll
                for (int ni = 0; ni < 2; ni++) {
                    uint32_t addr = bbase +
                        (uint32_t)((wn * 32 + ni * 16 + (lane & 15)) * BKp + k0 + ((lane >> 4) << 3)) * 2;
                    ldsm4(&bf[ni * 4], addr);
                }
                #pragma unroll
                for (int mi = 0; mi < 4; mi++) {
                    #pragma unroll
                    for (int nj = 0; nj < 4; nj++) {
                        uint32_t b2[2] = { bf[(nj >> 1) * 4 + (nj & 1)],
                                           bf[(nj >> 1) * 4 + (nj & 1) + 2] };
                        mma16816(acc[mi * 4 + nj], af[mi], b2);
                    }
                }
            }
        }
        __syncthreads();
    }

    #pragma unroll
    for (int mi = 0; mi < 4; mi++) {
        const int r0 = bm + wm * 64 + mi * 16 + (lane >> 2);
        #pragma unroll
        for (int nj = 0; nj < 4; nj++) {
            const int col = bn + wn * 32 + nj * 8 + (lane & 3) * 2;
            float* d = acc[mi * 4 + nj];
            *(float2*)&C[(size_t)r0 * N + col]       = make_float2(d[0], d[1]);
            *(float2*)&C[(size_t)(r0 + 8) * N + col] = make_float2(d[2], d[3]);
        }
    }
}

// ---------------- split fp32 -> (hi, lo) bf16, same layout ----------------
__global__ void split_rows_kernel(const float4* __restrict__ X,
                                  __nv_bfloat162* __restrict__ H,
                                  __nv_bfloat162* __restrict__ L, int n4)
{
    int i = blockIdx.x * blockDim.x + threadIdx.x;
    if (i >= n4) return;
    float4 v = X[i];
    __nv_bfloat16 h0 = __float2bfloat16(v.x), h1 = __float2bfloat16(v.y);
    __nv_bfloat16 h2 = __float2bfloat16(v.z), h3 = __float2bfloat16(v.w);
    H[2*i]   = __nv_bfloat162(h0, h1);
    H[2*i+1] = __nv_bfloat162(h2, h3);
    L[2*i]   = __nv_bfloat162(__float2bfloat16(v.x - __bfloat162float(h0)),
                              __float2bfloat16(v.y - __bfloat162float(h1)));
    L[2*i+1] = __nv_bfloat162(__float2bfloat16(v.z - __bfloat162float(h2)),
                              __float2bfloat16(v.w - __bfloat162float(h3)));
}

// ------- transpose + split: W[K,N] fp32 -> BT_h/BT_l [Npad,K] bf16 (pad=0) -------
__global__ void split_T_kernel(const float* __restrict__ W,
                               __nv_bfloat16* __restrict__ BTh,
                               __nv_bfloat16* __restrict__ BTl, int K, int N)
{
    __shared__ float t[32][33];
    const int k0 = blockIdx.y * 32, n0 = blockIdx.x * 32;
    const int tx = threadIdx.x, ty = threadIdx.y;
    #pragma unroll
    for (int i = 0; i < 32; i += 8) {
        int n = n0 + tx;
        t[ty + i][tx] = (n < N) ? W[(size_t)(k0 + ty + i) * N + n] : 0.f;
    }
    __syncthreads();
    #pragma unroll
    for (int i = 0; i < 32; i += 8) {
        int n = n0 + ty + i, k = k0 + tx;
        float v = t[tx][ty + i];
        __nv_bfloat16 hi = __float2bfloat16(v);
        BTh[(size_t)n * K + k] = hi;
        BTl[(size_t)n * K + k] = __float2bfloat16(v - __bfloat162float(hi));
    }
}

// ---------------- prep: rope(q), rope(k_rope), layernorm(kv_lat) ----------------
__global__ __launch_bounds__(128) void prep_kernel(
    const float* __restrict__ fc, const float* __restrict__ lnw, const float* __restrict__ lnb)
{
    const int tok = blockIdx.x;
    const int s   = tok & (Ss - 1);
    const int tid = threadIdx.x;

    const float* x = &g_kva[(size_t)tok * KVA_PAD];
    float local[4];
    float sum = 0.f;
    #pragma unroll
    for (int i = 0; i < 4; i++) { local[i] = x[tid + i * 128]; sum += local[i]; }
    __shared__ float red[4];
    #pragma unroll
    for (int o = 16; o > 0; o >>= 1) sum += __shfl_xor_sync(0xffffffffu, sum, o);
    if ((tid & 31) == 0) red[tid >> 5] = sum;
    __syncthreads();
    const float mean = (red[0] + red[1] + red[2] + red[3]) * (1.f / 512.f);
    float vs = 0.f;
    #pragma unroll
    for (int i = 0; i < 4; i++) { float d = local[i] - mean; vs = fmaf(d, d, vs); }
    #pragma unroll
    for (int o = 16; o > 0; o >>= 1) vs += __shfl_xor_sync(0xffffffffu, vs, o);
    __syncthreads();
    if ((tid & 31) == 0) red[tid >> 5] = vs;
    __syncthreads();
    const float var  = (red[0] + red[1] + red[2] + red[3]) * (1.f / 512.f);
    const float rstd = rsqrtf(var + LN_EPS);
    #pragma unroll
    for (int i = 0; i < 4; i++) {
        int c = tid + i * 128;
        float v = (local[i] - mean) * rstd * lnw[c] + lnb[c];
        __nv_bfloat16 hi = __float2bfloat16(v);
        g_kvlat_h[(size_t)tok * KVRANK + c] = hi;
        g_kvlat_l[(size_t)tok * KVRANK + c] = __float2bfloat16(v - __bfloat162float(hi));
    }

    const float* fcs = &fc[(size_t)s * 64];
    if (tid < 32) {
        float c  = fcs[tid * 2 + 0];
        float sn = fcs[tid * 2 + 1];
        float x0 = x[KVRANK + 2 * tid];
        float x1 = x[KVRANK + 2 * tid + 1];
        g_krope[(size_t)tok * DROPE + 2 * tid]     = x0 * c - x1 * sn;
        g_krope[(size_t)tok * DROPE + 2 * tid + 1] = x0 * sn + x1 * c;
    }
    #pragma unroll
    for (int i = 0; i < 4; i++) {
        int p  = tid + i * 128;
        int h  = p >> 5;
        int pi = p & 31;
        float c  = fcs[pi * 2 + 0];
        float sn = fcs[pi * 2 + 1];
        size_t base = (size_t)tok * (NHh * DQK) + h * DQK + DNOPE + 2 * pi;
        float x0 = g_q[base], x1 = g_q[base + 1];
        g_q[base]     = x0 * c - x1 * sn;
        g_q[base + 1] = x0 * sn + x1 * c;
    }
}

// ---------------- flash attention (SIMT fp32), writes bf16 split ----------------
#define QPAD 193
__global__ __launch_bounds__(256) void flash_kernel()
{
    const int qt  = (int)gridDim.x - 1 - (int)blockIdx.x;
    const int bh  = blockIdx.y;
    const int b   = bh >> 4;
    const int h   = bh & 15;
    const int tid = threadIdx.x;
    const int tx  = tid & 15;
    const int ty  = tid >> 4;

    extern __shared__ float sm[];
    float* Qs = sm;
    float* Ks = sm + 64 * QPAD;
    float* Vs = sm + 2 * 64 * QPAD;
    float* Ps = Vs + 64 * 128;

    const int q0 = qt * 64;
    const size_t tok0 = (size_t)b * Ss;

    for (int idx = tid; idx < 64 * 48; idx += 256) {
        int row = idx / 48, d4 = idx % 48;
        float4 v = *(const float4*)&g_q[(tok0 + q0 + row) * (NHh * DQK) + h * DQK + d4 * 4];
        Qs[row * QPAD + d4 * 4 + 0] = v.x;
        Qs[row * QPAD + d4 * 4 + 1] = v.y;
        Qs[row * QPAD + d4 * 4 + 2] = v.z;
        Qs[row * QPAD + d4 * 4 + 3] = v.w;
    }

    float o[4][8];
    #pragma unroll
    for (int r = 0; r < 4; r++)
        #pragma unroll
        for (int k = 0; k < 8; k++) o[r][k] = 0.f;
    float m[4] = {-1e30f, -1e30f, -1e30f, -1e30f};
    float l[4] = {0.f, 0.f, 0.f, 0.f};

    for (int jt = 0; jt <= qt; jt++) {
        const int j0 = jt * 64;
        for (int idx = tid; idx < 64 * 48; idx += 256) {
            int row = idx / 48, d4 = idx % 48;
            float4 v;
            if (d4 < 32)
                v = *(const float4*)&g_kv[(tok0 + j0 + row) * (NHh * 256) + h * 256 + d4 * 4];
            else
                v = *(const float4*)&g_krope[(tok0 + j0 + row) * DROPE + (d4 - 32) * 4];
            Ks[row * QPAD + d4 * 4 + 0] = v.x;
            Ks[row * QPAD + d4 * 4 + 1] = v.y;
            Ks[row * QPAD + d4 * 4 + 2] = v.z;
            Ks[row * QPAD + d4 * 4 + 3] = v.w;
        }
        __syncthreads();

        float sacc[4][4];
        #pragma unroll
        for (int r = 0; r < 4; r++)
            #pragma unroll
            for (int c = 0; c < 4; c++) sacc[r][c] = 0.f;
        #pragma unroll 4
        for (int d = 0; d < DQK; d++) {
            float qr[4], kr[4];
            #pragma unroll
            for (int r = 0; r < 4; r++) qr[r] = Qs[(ty * 4 + r) * QPAD + d];
            #pragma unroll
            for (int c = 0; c < 4; c++) kr[c] = Ks[(tx * 4 + c) * QPAD + d];
            #pragma unroll
            for (int r = 0; r < 4; r++)
                #pragma unroll
                for (int c = 0; c < 4; c++)
                    sacc[r][c] = fmaf(qr[r], kr[c], sacc[r][c]);
        }

        const bool diag = (jt == qt);
        #pragma unroll
        for (int r = 0; r < 4; r++) {
            const int gi = ty * 4 + r;
            float mx = -1e30f;
            #pragma unroll
            for (int c = 0; c < 4; c++) {
                float sv = sacc[r][c] * ATT_SCALE;
                if (diag && (tx * 4 + c) > gi) sv = -1e30f;
                sacc[r][c] = sv;
                mx = fmaxf(mx, sv);
            }
            #pragma unroll
            for (int o2 = 8; o2 > 0; o2 >>= 1)
                mx = fmaxf(mx, __shfl_xor_sync(0xffffffffu, mx, o2));
            const float mn = fmaxf(m[r], mx);
            const float alpha = __expf(m[r] - mn);
            float rs = 0.f;
            #pragma unroll
            for (int c = 0; c < 4; c++) {
                float p = __expf(sacc[r][c] - mn);
                rs += p;
                Ps[gi * 65 + tx * 4 + c] = p;
            }
            #pragma unroll
            for (int o2 = 8; o2 > 0; o2 >>= 1)
                rs += __shfl_xor_sync(0xffffffffu, rs, o2);
            l[r] = l[r] * alpha + rs;
            m[r] = mn;
            #pragma unroll
            for (int k = 0; k < 8; k++) o[r][k] *= alpha;
        }
        __syncthreads();

        for (int idx = tid; idx < 64 * 32; idx += 256) {
            int row = idx >> 5, d4 = idx & 31;
            *(float4*)&Vs[row * 128 + d4 * 4] =
                *(const float4*)&g_kv[(tok0 + j0 + row) * (NHh * 256) + h * 256 + 128 + d4 * 4];
        }
        __syncthreads();

        #pragma unroll 2
        for (int j = 0; j < 64; j++) {
            float pr[4];
            #pragma unroll
            for (int r = 0; r < 4; r++) pr[r] = Ps[(ty * 4 + r) * 65 + j];
            float4 v0 = *(const float4*)&Vs[j * 128 + tx * 8];
            float4 v1 = *(const float4*)&Vs[j * 128 + tx * 8 + 4];
            float vr[8] = {v0.x, v0.y, v0.z, v0.w, v1.x, v1.y, v1.z, v1.w};
            #pragma unroll
            for (int r = 0; r < 4; r++)
                #pragma unroll
                for (int k = 0; k < 8; k++)
                    o[r][k] = fmaf(pr[r], vr[k], o[r][k]);
        }
        __syncthreads();
    }

    #pragma unroll
    for (int r = 0; r < 4; r++) {
        const float inv = 1.f / l[r];
        const int row = q0 + ty * 4 + r;
        size_t base = (tok0 + row) * (NHh * DVv) + h * DVv + tx * 8;
        #pragma unroll
        for (int k = 0; k < 8; k++) {
            float v = o[r][k] * inv;
            __nv_bfloat16 hi = __float2bfloat16(v);
            g_attn_h[base + k] = hi;
            g_attn_l[base + k] = __float2bfloat16(v - __bfloat162float(hi));
        }
    }
}

// ---------------- launch ----------------
extern "C" void kernel_launch(void* const* d_in, const int* in_sizes, int n_in,
                              void* d_out, int out_size)
{
    const float* hs   = (const float*)d_in[0];
    const float* fc   = (const float*)d_in[1];
    const float* Wq   = (const float*)d_in[3];
    const float* Wkva = (const float*)d_in[4];
    const float* lnw  = (const float*)d_in[5];
    const float* lnb  = (const float*)d_in[6];
    const float* Wkvb = (const float*)d_in[7];
    const float* Wo   = (const float*)d_in[8];
    float* out = (float*)d_out;

    static bool init_done = false;
    static float *p_q, *p_kva, *p_kv;
    static __nv_bfloat16 *p_hs_h, *p_hs_l, *p_WqT_h, *p_WqT_l, *p_WkvaT_h, *p_WkvaT_l,
                         *p_WkvbT_h, *p_WkvbT_l, *p_WoT_h, *p_WoT_l,
                         *p_kvlat_h, *p_kvlat_l, *p_attn_h, *p_attn_l;
    static int smem_flash = 0;
    if (!init_done) {
        cudaGetSymbolAddress((void**)&p_q,      g_q);
        cudaGetSymbolAddress((void**)&p_kva,    g_kva);
        cudaGetSymbolAddress((void**)&p_kv,     g_kv);
        cudaGetSymbolAddress((void**)&p_hs_h,   g_hs_h);
        cudaGetSymbolAddress((void**)&p_hs_l,   g_hs_l);
        cudaGetSymbolAddress((void**)&p_WqT_h,  g_WqT_h);
        cudaGetSymbolAddress((void**)&p_WqT_l,  g_WqT_l);
        cudaGetSymbolAddress((void**)&p_WkvaT_h,g_WkvaT_h);
        cudaGetSymbolAddress((void**)&p_WkvaT_l,g_WkvaT_l);
        cudaGetSymbolAddress((void**)&p_WkvbT_h,g_WkvbT_h);
        cudaGetSymbolAddress((void**)&p_WkvbT_l,g_WkvbT_l);
        cudaGetSymbolAddress((void**)&p_WoT_h,  g_WoT_h);
        cudaGetSymbolAddress((void**)&p_WoT_l,  g_WoT_l);
        cudaGetSymbolAddress((void**)&p_kvlat_h,g_kvlat_h);
        cudaGetSymbolAddress((void**)&p_kvlat_l,g_kvlat_l);
        cudaGetSymbolAddress((void**)&p_attn_h, g_attn_h);
        cudaGetSymbolAddress((void**)&p_attn_l, g_attn_l);
        smem_flash = (2 * 64 * QPAD + 64 * 128 + 64 * 65) * (int)sizeof(float);
        cudaFuncSetAttribute(flash_kernel,
                             cudaFuncAttributeMaxDynamicSharedMemorySize, smem_flash);
        cudaFuncSetAttribute(mma_gemm,
                             cudaFuncAttributeMaxDynamicSharedMemorySize, GS_SMEM);
        init_done = true;
    }

    // 0) split operands to bf16 hi/lo
    {
        int n4 = NTOK * HIDc / 4;
        split_rows_kernel<<<(n4 + 255) / 256, 256>>>(
            (const float4*)hs, (__nv_bfloat162*)p_hs_h, (__nv_bfloat162*)p_hs_l, n4);
    }
    split_T_kernel<<<dim3(3072/32, HIDc/32),   dim3(32,8)>>>(Wq,   p_WqT_h,   p_WqT_l,   HIDc,   3072);
    split_T_kernel<<<dim3(KVA_PAD/32, HIDc/32),dim3(32,8)>>>(Wkva, p_WkvaT_h, p_WkvaT_l, HIDc,   576);
    split_T_kernel<<<dim3(4096/32, KVRANK/32), dim3(32,8)>>>(Wkvb, p_WkvbT_h, p_WkvbT_l, KVRANK, 4096);
    split_T_kernel<<<dim3(2048/32, HIDc/32),   dim3(32,8)>>>(Wo,   p_WoT_h,   p_WoT_l,   HIDc,   2048);

    // 1) q = hidden @ Wq           [4096, 3072]
    mma_gemm<<<dim3(3072/128, NTOK/128), 256, GS_SMEM>>>(p_hs_h, p_hs_l, p_WqT_h, p_WqT_l, p_q, NTOK, 3072, HIDc);
    // 2) kv_a = hidden @ Wkv_a     [4096, 640] (padded)
    mma_gemm<<<dim3(KVA_PAD/128, NTOK/128), 256, GS_SMEM>>>(p_hs_h, p_hs_l, p_WkvaT_h, p_WkvaT_l, p_kva, NTOK, KVA_PAD, HIDc);
    // 3) rope + layernorm
    prep_kernel<<<NTOK, 128>>>(fc, lnw, lnb);
    // 4) kv = kv_lat @ Wkv_b       [4096, 4096]
    mma_gemm<<<dim3(4096/128, NTOK/128), 256, GS_SMEM>>>(p_kvlat_h, p_kvlat_l, p_WkvbT_h, p_WkvbT_l, p_kv, NTOK, 4096, KVRANK);
    // 5) flash attention
    flash_kernel<<<dim3(Ss/64, Bb*NHh), 256, smem_flash>>>();
    // 6) out = attn @ Wo           [4096, 2048]
    mma_gemm<<<dim3(2048/128, NTOK/128), 256, GS_SMEM>>>(p_attn_h, p_attn_l, p_WoT_h, p_WoT_l, out, NTOK, 2048, HIDc);
}

// round 4
// speedup vs baseline: 2.6488x; 1.8206x over previous
#include <cuda_runtime.h>
#include <cuda_bf16.h>
#include <math.h>
#include <stdint.h>

// ---------------- problem constants ----------------
#define Bb      2
#define Ss      2048
#define HIDc    2048
#define NHh     16
#define DNOPE   128
#define DROPE   64
#define DVv     128
#define DQK     192
#define KVRANK  512
#define NTOK    (Bb*Ss)            // 4096
#define KVA_PAD 640
#define ATT_SCALE 0.072168783648703220563f
#define QSCALE (0.072168783648703220563f * 1.4426950408889634f)   // fold log2(e)
#define LN_EPS 1e-5f

// ---------------- scratch (static device globals) ----------------
__device__ float g_q    [(size_t)NTOK * NHh * DQK];
__device__ float g_kva  [(size_t)NTOK * KVA_PAD];
__device__ float g_krope[(size_t)NTOK * DROPE];
__device__ float g_kv   [(size_t)NTOK * NHh * (DNOPE+DVv)];
// bf16 split operands for GEMMs
__device__ __nv_bfloat16 g_hs_h [(size_t)NTOK * HIDc];
__device__ __nv_bfloat16 g_hs_l [(size_t)NTOK * HIDc];
__device__ __nv_bfloat16 g_WqT_h [(size_t)3072 * HIDc];
__device__ __nv_bfloat16 g_WqT_l [(size_t)3072 * HIDc];
__device__ __nv_bfloat16 g_WkvaT_h[(size_t)KVA_PAD * HIDc];
__device__ __nv_bfloat16 g_WkvaT_l[(size_t)KVA_PAD * HIDc];
__device__ __nv_bfloat16 g_WkvbT_h[(size_t)4096 * KVRANK];
__device__ __nv_bfloat16 g_WkvbT_l[(size_t)4096 * KVRANK];
__device__ __nv_bfloat16 g_WoT_h [(size_t)HIDc * HIDc];
__device__ __nv_bfloat16 g_WoT_l [(size_t)HIDc * HIDc];
__device__ __nv_bfloat16 g_kvlat_h[(size_t)NTOK * KVRANK];
__device__ __nv_bfloat16 g_kvlat_l[(size_t)NTOK * KVRANK];
__device__ __nv_bfloat16 g_attn_h[(size_t)NTOK * NHh * DVv];
__device__ __nv_bfloat16 g_attn_l[(size_t)NTOK * NHh * DVv];
// bf16 split operands for attention, head-major [h][tok][d]
__device__ __nv_bfloat16 g_qh[(size_t)NHh * NTOK * DQK];
__device__ __nv_bfloat16 g_ql[(size_t)NHh * NTOK * DQK];
__device__ __nv_bfloat16 g_kh[(size_t)NHh * NTOK * DQK];
__device__ __nv_bfloat16 g_kl[(size_t)NHh * NTOK * DQK];
__device__ __nv_bfloat16 g_vh[(size_t)NHh * NTOK * DVv];
__device__ __nv_bfloat16 g_vl[(size_t)NHh * NTOK * DVv];

// ================= helpers =================
__device__ __forceinline__ uint32_t smem_u32(const void* p) {
    uint32_t a;
    asm("{ .reg .u64 t; cvta.to.shared.u64 t, %1; cvt.u32.u64 %0, t; }" : "=r"(a) : "l"(p));
    return a;
}
__device__ __forceinline__ void ldsm4(uint32_t* r, uint32_t addr) {
    asm volatile("ldmatrix.sync.aligned.m8n8.x4.shared.b16 {%0,%1,%2,%3}, [%4];"
        : "=r"(r[0]), "=r"(r[1]), "=r"(r[2]), "=r"(r[3]) : "r"(addr));
}
__device__ __forceinline__ void ldsm4t(uint32_t* r, uint32_t addr) {
    asm volatile("ldmatrix.sync.aligned.m8n8.x4.trans.shared.b16 {%0,%1,%2,%3}, [%4];"
        : "=r"(r[0]), "=r"(r[1]), "=r"(r[2]), "=r"(r[3]) : "r"(addr));
}
__device__ __forceinline__ void mma16816(float* d, const uint32_t* a, const uint32_t* b) {
    asm volatile("mma.sync.aligned.m16n8k16.row.col.f32.bf16.bf16.f32 "
        "{%0,%1,%2,%3}, {%4,%5,%6,%7}, {%8,%9}, {%0,%1,%2,%3};"
        : "+f"(d[0]), "+f"(d[1]), "+f"(d[2]), "+f"(d[3])
        : "r"(a[0]), "r"(a[1]), "r"(a[2]), "r"(a[3]), "r"(b[0]), "r"(b[1]));
}
__device__ __forceinline__ float ex2f(float x) {
    float y; asm("ex2.approx.f32 %0, %1;" : "=f"(y) : "f"(x)); return y;
}
__device__ __forceinline__ uint32_t pk2(__nv_bfloat16 a, __nv_bfloat16 b) {
    __nv_bfloat162 t(a, b); return *reinterpret_cast<uint32_t*>(&t);
}

// ============ mma.sync bf16-split GEMM (unchanged, proven) ============
#define BKp     40
#define TILE_B  (128 * BKp * 2)
#define STAGE_B (4 * TILE_B)
#define GS_SMEM (2 * STAGE_B)

__global__ __launch_bounds__(256) void mma_gemm(
    const __nv_bfloat16* __restrict__ Ah, const __nv_bfloat16* __restrict__ Al,
    const __nv_bfloat16* __restrict__ Bh, const __nv_bfloat16* __restrict__ Bl,
    float* __restrict__ C, int M, int N, int K)
{
    extern __shared__ char dsm[];
    const uint32_t sbase = smem_u32(dsm);
    const int tid = threadIdx.x, wid = tid >> 5, lane = tid & 31;
    const int wm = wid >> 2, wn = wid & 3;
    const int bm = blockIdx.y * 128, bn = blockIdx.x * 128;

    const __nv_bfloat16* srcs[4] = {
        Ah + (size_t)bm * K, Al + (size_t)bm * K,
        Bh + (size_t)bn * K, Bl + (size_t)bn * K };

    auto load_chunk = [&](int c, int s) {
        #pragma unroll
        for (int t = 0; t < 4; t++) {
            const __nv_bfloat16* src = srcs[t] + c * 32;
            uint32_t tb = sbase + s * STAGE_B + t * TILE_B;
            #pragma unroll
            for (int i = 0; i < 2; i++) {
                int u = tid + i * 256;
                int row = u >> 2, c8 = u & 3;
                const void* g = src + (size_t)row * K + c8 * 8;
                uint32_t d = tb + (uint32_t)(row * BKp + c8 * 8) * 2;
                asm volatile("cp.async.cg.shared.global [%0], [%1], 16;" :: "r"(d), "l"(g));
            }
        }
        asm volatile("cp.async.commit_group;" ::: "memory");
    };

    float acc[16][4];
    #pragma unroll
    for (int i = 0; i < 16; i++)
        #pragma unroll
        for (int j = 0; j < 4; j++) acc[i][j] = 0.f;

    const int nchunk = K >> 5;
    load_chunk(0, 0);

    for (int c = 0; c < nchunk; c++) {
        const int s = c & 1;
        if (c + 1 < nchunk) {
            load_chunk(c + 1, s ^ 1);
            asm volatile("cp.async.wait_group 1;" ::: "memory");
        } else {
            asm volatile("cp.async.wait_group 0;" ::: "memory");
        }
        __syncthreads();
        const uint32_t stg = sbase + s * STAGE_B;
        #pragma unroll
        for (int ks = 0; ks < 2; ks++) {
            const int k0 = ks * 16;
            #pragma unroll
            for (int t = 0; t < 3; t++) {
                const int at = (t == 2) ? 1 : 0;
                const int bt = (t == 1) ? 3 : 2;
                const uint32_t abase = stg + at * TILE_B;
                const uint32_t bbase = stg + bt * TILE_B;
                uint32_t af[4][4], bf[8];
                #pragma unroll
                for (int mi = 0; mi < 4; mi++) {
                    uint32_t addr = abase +
                        (uint32_t)((wm * 64 + mi * 16 + (lane & 15)) * BKp + k0 + ((lane >> 4) << 3)) * 2;
                    ldsm4(af[mi], addr);
                }
                #pragma unroll
                for (int ni = 0; ni < 2; ni++) {
                    uint32_t addr = bbase +
                        (uint32_t)((wn * 32 + ni * 16 + (lane & 15)) * BKp + k0 + ((lane >> 4) << 3)) * 2;
                    ldsm4(&bf[ni * 4], addr);
                }
                #pragma unroll
                for (int mi = 0; mi < 4; mi++) {
                    #pragma unroll
                    for (int nj = 0; nj < 4; nj++) {
                        uint32_t b2[2] = { bf[(nj >> 1) * 4 + (nj & 1)],
                                           bf[(nj >> 1) * 4 + (nj & 1) + 2] };
                        mma16816(acc[mi * 4 + nj], af[mi], b2);
                    }
                }
            }
        }
        __syncthreads();
    }

    #pragma unroll
    for (int mi = 0; mi < 4; mi++) {
        const int r0 = bm + wm * 64 + mi * 16 + (lane >> 2);
        #pragma unroll
        for (int nj = 0; nj < 4; nj++) {
            const int col = bn + wn * 32 + nj * 8 + (lane & 3) * 2;
            float* d = acc[mi * 4 + nj];
            *(float2*)&C[(size_t)r0 * N + col]       = make_float2(d[0], d[1]);
            *(float2*)&C[(size_t)(r0 + 8) * N + col] = make_float2(d[2], d[3]);
        }
    }
}

// ---------------- split fp32 -> (hi, lo) bf16 ----------------
__global__ void split_rows_kernel(const float4* __restrict__ X,
                                  __nv_bfloat162* __restrict__ H,
                                  __nv_bfloat162* __restrict__ L, int n4)
{
    int i = blockIdx.x * blockDim.x + threadIdx.x;
    if (i >= n4) return;
    float4 v = X[i];
    __nv_bfloat16 h0 = __float2bfloat16(v.x), h1 = __float2bfloat16(v.y);
    __nv_bfloat16 h2 = __float2bfloat16(v.z), h3 = __float2bfloat16(v.w);
    H[2*i]   = __nv_bfloat162(h0, h1);
    H[2*i+1] = __nv_bfloat162(h2, h3);
    L[2*i]   = __nv_bfloat162(__float2bfloat16(v.x - __bfloat162float(h0)),
                              __float2bfloat16(v.y - __bfloat162float(h1)));
    L[2*i+1] = __nv_bfloat162(__float2bfloat16(v.z - __bfloat162float(h2)),
                              __float2bfloat16(v.w - __bfloat162float(h3)));
}

__global__ void split_T_kernel(const float* __restrict__ W,
                               __nv_bfloat16* __restrict__ BTh,
                               __nv_bfloat16* __restrict__ BTl, int K, int N)
{
    __shared__ float t[32][33];
    const int k0 = blockIdx.y * 32, n0 = blockIdx.x * 32;
    const int tx = threadIdx.x, ty = threadIdx.y;
    #pragma unroll
    for (int i = 0; i < 32; i += 8) {
        int n = n0 + tx;
        t[ty + i][tx] = (n < N) ? W[(size_t)(k0 + ty + i) * N + n] : 0.f;
    }
    __syncthreads();
    #pragma unroll
    for (int i = 0; i < 32; i += 8) {
        int n = n0 + ty + i, k = k0 + tx;
        float v = t[tx][ty + i];
        __nv_bfloat16 hi = __float2bfloat16(v);
        BTh[(size_t)n * K + k] = hi;
        BTl[(size_t)n * K + k] = __float2bfloat16(v - __bfloat162float(hi));
    }
}

// ---------------- prep: LN(kv_lat) + rope(k_rope) + rope+scale+split(q) ----------------
__global__ __launch_bounds__(128) void prep_kernel(
    const float* __restrict__ fc, const float* __restrict__ lnw, const float* __restrict__ lnb)
{
    const int tok = blockIdx.x;
    const int s   = tok & (Ss - 1);
    const int tid = threadIdx.x;

    const float* x = &g_kva[(size_t)tok * KVA_PAD];
    float local[4];
    float sum = 0.f;
    #pragma unroll
    for (int i = 0; i < 4; i++) { local[i] = x[tid + i * 128]; sum += local[i]; }
    __shared__ float red[4];
    #pragma unroll
    for (int o = 16; o > 0; o >>= 1) sum += __shfl_xor_sync(0xffffffffu, sum, o);
    if ((tid & 31) == 0) red[tid >> 5] = sum;
    __syncthreads();
    const float mean = (red[0] + red[1] + red[2] + red[3]) * (1.f / 512.f);
    float vs = 0.f;
    #pragma unroll
    for (int i = 0; i < 4; i++) { float d = local[i] - mean; vs = fmaf(d, d, vs); }
    #pragma unroll
    for (int o = 16; o > 0; o >>= 1) vs += __shfl_xor_sync(0xffffffffu, vs, o);
    __syncthreads();
    if ((tid & 31) == 0) red[tid >> 5] = vs;
    __syncthreads();
    const float var  = (red[0] + red[1] + red[2] + red[3]) * (1.f / 512.f);
    const float rstd = rsqrtf(var + LN_EPS);
    #pragma unroll
    for (int i = 0; i < 4; i++) {
        int c = tid + i * 128;
        float v = (local[i] - mean) * rstd * lnw[c] + lnb[c];
        __nv_bfloat16 hi = __float2bfloat16(v);
        g_kvlat_h[(size_t)tok * KVRANK + c] = hi;
        g_kvlat_l[(size_t)tok * KVRANK + c] = __float2bfloat16(v - __bfloat162float(hi));
    }

    const float* fcs = &fc[(size_t)s * 64];
    if (tid < 32) {
        float c  = fcs[tid * 2 + 0];
        float sn = fcs[tid * 2 + 1];
        float x0 = x[KVRANK + 2 * tid];
        float x1 = x[KVRANK + 2 * tid + 1];
        g_krope[(size_t)tok * DROPE + 2 * tid]     = x0 * c - x1 * sn;
        g_krope[(size_t)tok * DROPE + 2 * tid + 1] = x0 * sn + x1 * c;
    }
    // q rope part: scale + split into head-major layout
    #pragma unroll
    for (int i = 0; i < 4; i++) {
        int p  = tid + i * 128;
        int hh = p >> 5;
        int pi = p & 31;
        float c  = fcs[pi * 2 + 0];
        float sn = fcs[pi * 2 + 1];
        size_t src = (size_t)tok * (NHh * DQK) + hh * DQK + DNOPE + 2 * pi;
        float x0 = g_q[src], x1 = g_q[src + 1];
        float y0 = (x0 * c - x1 * sn) * QSCALE;
        float y1 = (x0 * sn + x1 * c) * QSCALE;
        size_t dst = ((size_t)hh * NTOK + tok) * DQK + DNOPE + 2 * pi;
        __nv_bfloat16 b0 = __float2bfloat16(y0), b1 = __float2bfloat16(y1);
        g_qh[dst] = b0;  g_qh[dst + 1] = b1;
        g_ql[dst]     = __float2bfloat16(y0 - __bfloat162float(b0));
        g_ql[dst + 1] = __float2bfloat16(y1 - __bfloat162float(b1));
    }
    // q nope part
    #pragma unroll
    for (int i = 0; i < 16; i++) {
        int e = tid + i * 128;
        int hh = e >> 7, d = e & 127;
        float v = g_q[(size_t)tok * (NHh * DQK) + hh * DQK + d] * QSCALE;
        size_t dst = ((size_t)hh * NTOK + tok) * DQK + d;
        __nv_bfloat16 b = __float2bfloat16(v);
        g_qh[dst] = b;
        g_ql[dst] = __float2bfloat16(v - __bfloat162float(b));
    }
}

// ---------------- kv split: g_kv + g_krope -> head-major K/V bf16 hi/lo ----------------
__global__ __launch_bounds__(256) void kv_split_kernel()
{
    const int tok = blockIdx.x;
    const int tid = threadIdx.x;
    #pragma unroll
    for (int i = 0; i < 16; i++) {
        int e = tid + i * 256;
        int hh = e >> 8, d = e & 255;
        float v = g_kv[(size_t)tok * 4096 + e];
        __nv_bfloat16 b = __float2bfloat16(v);
        __nv_bfloat16 r = __float2bfloat16(v - __bfloat162float(b));
        if (d < 128) {
            size_t dst = ((size_t)hh * NTOK + tok) * DQK + d;
            g_kh[dst] = b; g_kl[dst] = r;
        } else {
            size_t dst = ((size_t)hh * NTOK + tok) * DVv + (d - 128);
            g_vh[dst] = b; g_vl[dst] = r;
        }
    }
    #pragma unroll
    for (int i = 0; i < 4; i++) {
        int e = tid + i * 256;
        int hh = e >> 6, k = e & 63;
        float v = g_krope[(size_t)tok * DROPE + k];
        __nv_bfloat16 b = __float2bfloat16(v);
        size_t dst = ((size_t)hh * NTOK + tok) * DQK + 128 + k;
        g_kh[dst] = b;
        g_kl[dst] = __float2bfloat16(v - __bfloat162float(b));
    }
}

// ---------------- flash attention on mma.sync, bf16 split ----------------
#define FQT 128
#define FKT 32
#define QKB 400            // bytes per Q/K smem row (200 bf16)
#define VB  272            // bytes per V smem row (136 bf16)
#define OQH 0
#define OQL 51200
#define OKH 102400
#define OKL 128000
#define OVH 153600
#define OVL 171008
#define KSTG 12800
#define VSTG 8704
#define FSMEM 188416

__global__ __launch_bounds__(256) void flash_mma()
{
    const int qt   = (int)gridDim.x - 1 - (int)blockIdx.x;
    const int bh   = blockIdx.y, b = bh >> 4, h = bh & 15;
    const int tid  = threadIdx.x, w = tid >> 5, lane = tid & 31;
    extern __shared__ char fsm[];
    const uint32_t sb = smem_u32(fsm);
    const int q0 = qt * FQT;
    const size_t rowQ = (size_t)h * NTOK + (size_t)b * Ss + q0;
    const size_t rowK = (size_t)h * NTOK + (size_t)b * Ss;

    // load Q (both splits) into smem
    #pragma unroll
    for (int i = 0; i < 24; i++) {
        int u = tid + i * 256;                  // 0..6143
        int sp = (u >= 3072); int uu = u - sp * 3072;
        int row = uu / 24, c = uu % 24;
        const void* src = (sp ? g_ql : g_qh) + (rowQ + row) * DQK + c * 8;
        uint32_t dst = sb + (sp ? OQL : OQH) + row * QKB + c * 16;
        asm volatile("cp.async.cg.shared.global [%0], [%1], 16;" :: "r"(dst), "l"(src));
    }

    auto load_kv = [&](int j, int st) {
        const int j0 = j * FKT;
        #pragma unroll
        for (int i = 0; i < 6; i++) {
            int u = tid + i * 256;              // 0..1535
            int sp = (u >= 768); int uu = u - sp * 768;
            int row = uu / 24, c = uu % 24;
            const void* src = (sp ? g_kl : g_kh) + (rowK + j0 + row) * DQK + c * 8;
            uint32_t dst = sb + (sp ? OKL : OKH) + st * KSTG + row * QKB + c * 16;
            asm volatile("cp.async.cg.shared.global [%0], [%1], 16;" :: "r"(dst), "l"(src));
        }
        #pragma unroll
        for (int i = 0; i < 4; i++) {
            int u = tid + i * 256;              // 0..1023
            int sp = (u >= 512); int uu = u - sp * 512;
            int row = uu >> 4, c = uu & 15;
            const void* src = (sp ? g_vl : g_vh) + (rowK + j0 + row) * DVv + c * 8;
            uint32_t dst = sb + (sp ? OVL : OVH) + st * VSTG + row * VB + c * 16;
            asm volatile("cp.async.cg.shared.global [%0], [%1], 16;" :: "r"(dst), "l"(src));
        }
        asm volatile("cp.async.commit_group;" ::: "memory");
    };
    load_kv(0, 0);

    float o[16][4];
    #pragma unroll
    for (int t = 0; t < 16; t++)
        #pragma unroll
        for (int e = 0; e < 4; e++) o[t][e] = 0.f;
    float mr[2] = {-1e30f, -1e30f}, lr[2] = {0.f, 0.f};

    const uint32_t q_off = sb + OQH + (w * 16 + (lane & 15)) * QKB + ((lane >> 4) << 4);
    const uint32_t kz = (lane & 15) * QKB + ((lane >> 4) << 4);
    const uint32_t vz = (lane & 15) * VB  + ((lane >> 4) << 4);
    const int nkt = q0 / FKT + 4;

    for (int j = 0; j < nkt; j++) {
        const int st = j & 1, j0 = j * FKT;
        if (j + 1 < nkt) {
            load_kv(j + 1, st ^ 1);
            asm volatile("cp.async.wait_group 1;" ::: "memory");
        } else {
            asm volatile("cp.async.wait_group 0;" ::: "memory");
        }
        __syncthreads();

        // --- S = Q K^T (3-term split) ---
        float sacc[4][4];
        #pragma unroll
        for (int t = 0; t < 4; t++)
            #pragma unroll
            for (int e = 0; e < 4; e++) sacc[t][e] = 0.f;

        #pragma unroll
        for (int ks = 0; ks < 12; ks++) {
            uint32_t qh4[4], ql4[4];
            ldsm4(qh4, q_off + ks * 32);
            ldsm4(ql4, q_off + (OQL - OQH) + ks * 32);
            #pragma unroll
            for (int nw = 0; nw < 2; nw++) {
                uint32_t kh4[4], kl4[4];
                uint32_t ka = sb + OKH + st * KSTG + nw * 16 * QKB + kz + ks * 32;
                ldsm4(kh4, ka);
                ldsm4(kl4, ka + (OKL - OKH));
                uint32_t bh0[2] = {kh4[0], kh4[2]}, bh1[2] = {kh4[1], kh4[3]};
                uint32_t bl0[2] = {kl4[0], kl4[2]}, bl1[2] = {kl4[1], kl4[3]};
                mma16816(sacc[nw * 2],     qh4, bh0);
                mma16816(sacc[nw * 2],     qh4, bl0);
                mma16816(sacc[nw * 2],     ql4, bh0);
                mma16816(sacc[nw * 2 + 1], qh4, bh1);
                mma16816(sacc[nw * 2 + 1], qh4, bl1);
                mma16816(sacc[nw * 2 + 1], ql4, bh1);
            }
        }

        // --- causal mask (diag tiles only) ---
        if (j0 + FKT - 1 > q0) {
            #pragma unroll
            for (int t = 0; t < 4; t++)
                #pragma unroll
                for (int e = 0; e < 4; e++) {
                    int rowg = q0 + w * 16 + (lane >> 2) + (e >> 1) * 8;
                    int colg = j0 + t * 8 + (lane & 3) * 2 + (e & 1);
                    if (colg > rowg) sacc[t][e] = -1e30f;
                }
        }

        // --- online softmax (per row-half; scores already in log2 units) ---
        float alpha[2];
        #pragma unroll
        for (int rh = 0; rh < 2; rh++) {
            float mx = -1e30f;
            #pragma unroll
            for (int t = 0; t < 4; t++)
                mx = fmaxf(mx, fmaxf(sacc[t][rh * 2], sacc[t][rh * 2 + 1]));
            mx = fmaxf(mx, __shfl_xor_sync(0xffffffffu, mx, 1));
            mx = fmaxf(mx, __shfl_xor_sync(0xffffffffu, mx, 2));
            float mn = fmaxf(mr[rh], mx);
            alpha[rh] = ex2f(mr[rh] - mn);
            mr[rh] = mn;
            float rs = 0.f;
            #pragma unroll
            for (int t = 0; t < 4; t++) {
                float p0 = ex2f(sacc[t][rh * 2]     - mn);
                float p1 = ex2f(sacc[t][rh * 2 + 1] - mn);
                sacc[t][rh * 2] = p0; sacc[t][rh * 2 + 1] = p1;
                rs += p0 + p1;
            }
            rs += __shfl_xor_sync(0xffffffffu, rs, 1);
            rs += __shfl_xor_sync(0xffffffffu, rs, 2);
            lr[rh] = lr[rh] * alpha[rh] + rs;
        }
        #pragma unroll
        for (int t = 0; t < 16; t++) {
            o[t][0] *= alpha[0]; o[t][1] *= alpha[0];
            o[t][2] *= alpha[1]; o[t][3] *= alpha[1];
        }

        // --- pack P into A-fragments (hi + lo), register-only ---
        uint32_t ah[2][4], al[2][4];
        #pragma unroll
        for (int ks2 = 0; ks2 < 2; ks2++) {
            #pragma unroll
            for (int q = 0; q < 4; q++) {
                int t = ks2 * 2 + (q >> 1);
                int e = (q & 1) * 2;
                float p0 = sacc[t][e], p1 = sacc[t][e + 1];
                __nv_bfloat16 h0 = __float2bfloat16(p0), h1 = __float2bfloat16(p1);
                ah[ks2][q] = pk2(h0, h1);
                al[ks2][q] = pk2(__float2bfloat16(p0 - __bfloat162float(h0)),
                                 __float2bfloat16(p1 - __bfloat162float(h1)));
            }
        }
        // NOTE: a-frag register order is a0={r,k0-7} a1={r+8,k0-7} a2={r,k8-15} a3={r+8,k8-15};
        // mapping above: q=0 -> t0 rows r (e=0,1) = a0; q=1 -> t0 rows r+8 = a1;
        // q=2 -> t1 rows r = a2; q=3 -> t1 rows r+8 = a3.  (t0 = cols k0-7, t1 = k8-15) OK.

        // --- O += P V (3-term split) ---
        #pragma unroll
        for (int ks2 = 0; ks2 < 2; ks2++) {
            #pragma unroll
            for (int nw = 0; nw < 8; nw++) {
                uint32_t vh4[4], vl4[4];
                uint32_t va = sb + OVH + st * VSTG + ks2 * 16 * VB + vz + nw * 32;
                ldsm4t(vh4, va);
                ldsm4t(vl4, va + (OVL - OVH));
                uint32_t b0h[2] = {vh4[0], vh4[1]}, b1h[2] = {vh4[2], vh4[3]};
                uint32_t b0l[2] = {vl4[0], vl4[1]}, b1l[2] = {vl4[2], vl4[3]};
                mma16816(o[nw * 2],     ah[ks2], b0h);
                mma16816(o[nw * 2],     al[ks2], b0h);
                mma16816(o[nw * 2],     ah[ks2], b0l);
                mma16816(o[nw * 2 + 1], ah[ks2], b1h);
                mma16816(o[nw * 2 + 1], al[ks2], b1h);
                mma16816(o[nw * 2 + 1], ah[ks2], b1l);
            }
        }
        __syncthreads();
    }

    // --- epilogue: normalize, split to bf16 hi/lo, store ---
    #pragma unroll
    for (int rh = 0; rh < 2; rh++) {
        float inv = 1.f / lr[rh];
        int row = q0 + w * 16 + (lane >> 2) + rh * 8;
        size_t gbase = ((size_t)b * Ss + row) * (NHh * DVv) + h * DVv;
        #pragma unroll
        for (int t = 0; t < 16; t++) {
            int d = t * 8 + (lane & 3) * 2;
            float v0 = o[t][rh * 2] * inv, v1 = o[t][rh * 2 + 1] * inv;
            __nv_bfloat16 h0 = __float2bfloat16(v0), h1 = __float2bfloat16(v1);
            *(uint32_t*)&g_attn_h[gbase + d] = pk2(h0, h1);
            *(uint32_t*)&g_attn_l[gbase + d] = pk2(__float2bfloat16(v0 - __bfloat162float(h0)),
                                                   __float2bfloat16(v1 - __bfloat162float(h1)));
        }
    }
}

// ---------------- launch ----------------
extern "C" void kernel_launch(void* const* d_in, const int* in_sizes, int n_in,
                              void* d_out, int out_size)
{
    const float* hs   = (const float*)d_in[0];
    const float* fc   = (const float*)d_in[1];
    const float* Wq   = (const float*)d_in[3];
    const float* Wkva = (const float*)d_in[4];
    const float* lnw  = (const float*)d_in[5];
    const float* lnb  = (const float*)d_in[6];
    const float* Wkvb = (const float*)d_in[7];
    const float* Wo   = (const float*)d_in[8];
    float* out = (float*)d_out;

    static bool init_done = false;
    static float *p_q, *p_kva, *p_kv;
    static __nv_bfloat16 *p_hs_h, *p_hs_l, *p_WqT_h, *p_WqT_l, *p_WkvaT_h, *p_WkvaT_l,
                         *p_WkvbT_h, *p_WkvbT_l, *p_WoT_h, *p_WoT_l,
                         *p_kvlat_h, *p_kvlat_l, *p_attn_h, *p_attn_l;
    if (!init_done) {
        cudaGetSymbolAddress((void**)&p_q,      g_q);
        cudaGetSymbolAddress((void**)&p_kva,    g_kva);
        cudaGetSymbolAddress((void**)&p_kv,     g_kv);
        cudaGetSymbolAddress((void**)&p_hs_h,   g_hs_h);
        cudaGetSymbolAddress((void**)&p_hs_l,   g_hs_l);
        cudaGetSymbolAddress((void**)&p_WqT_h,  g_WqT_h);
        cudaGetSymbolAddress((void**)&p_WqT_l,  g_WqT_l);
        cudaGetSymbolAddress((void**)&p_WkvaT_h,g_WkvaT_h);
        cudaGetSymbolAddress((void**)&p_WkvaT_l,g_WkvaT_l);
        cudaGetSymbolAddress((void**)&p_WkvbT_h,g_WkvbT_h);
        cudaGetSymbolAddress((void**)&p_WkvbT_l,g_WkvbT_l);
        cudaGetSymbolAddress((void**)&p_WoT_h,  g_WoT_h);
        cudaGetSymbolAddress((void**)&p_WoT_l,  g_WoT_l);
        cudaGetSymbolAddress((void**)&p_kvlat_h,g_kvlat_h);
        cudaGetSymbolAddress((void**)&p_kvlat_l,g_kvlat_l);
        cudaGetSymbolAddress((void**)&p_attn_h, g_attn_h);
        cudaGetSymbolAddress((void**)&p_attn_l, g_attn_l);
        cudaFuncSetAttribute(mma_gemm,
                             cudaFuncAttributeMaxDynamicSharedMemorySize, GS_SMEM);
        cudaFuncSetAttribute(flash_mma,
                             cudaFuncAttributeMaxDynamicSharedMemorySize, FSMEM);
        init_done = true;
    }

    // 0) splits of inputs
    {
        int n4 = NTOK * HIDc / 4;
        split_rows_kernel<<<(n4 + 255) / 256, 256>>>(
            (const float4*)hs, (__nv_bfloat162*)p_hs_h, (__nv_bfloat162*)p_hs_l, n4);
    }
    split_T_kernel<<<dim3(3072/32, HIDc/32),   dim3(32,8)>>>(Wq,   p_WqT_h,   p_WqT_l,   HIDc,   3072);
    split_T_kernel<<<dim3(KVA_PAD/32, HIDc/32),dim3(32,8)>>>(Wkva, p_WkvaT_h, p_WkvaT_l, HIDc,   576);
    split_T_kernel<<<dim3(4096/32, KVRANK/32), dim3(32,8)>>>(Wkvb, p_WkvbT_h, p_WkvbT_l, KVRANK, 4096);
    split_T_kernel<<<dim3(2048/32, HIDc/32),   dim3(32,8)>>>(Wo,   p_WoT_h,   p_WoT_l,   HIDc,   2048);

    // 1) q = hidden @ Wq
    mma_gemm<<<dim3(3072/128, NTOK/128), 256, GS_SMEM>>>(p_hs_h, p_hs_l, p_WqT_h, p_WqT_l, p_q, NTOK, 3072, HIDc);
    // 2) kv_a = hidden @ Wkv_a
    mma_gemm<<<dim3(KVA_PAD/128, NTOK/128), 256, GS_SMEM>>>(p_hs_h, p_hs_l, p_WkvaT_h, p_WkvaT_l, p_kva, NTOK, KVA_PAD, HIDc);
    // 3) prep (LN + rope + q split)
    prep_kernel<<<NTOK, 128>>>(fc, lnw, lnb);
    // 4) kv = kv_lat @ Wkv_b
    mma_gemm<<<dim3(4096/128, NTOK/128), 256, GS_SMEM>>>(p_kvlat_h, p_kvlat_l, p_WkvbT_h, p_WkvbT_l, p_kv, NTOK, 4096, KVRANK);
    // 5) split kv -> head-major K/V bf16
    kv_split_kernel<<<NTOK, 256>>>();
    // 6) flash attention (tensor cores)
    flash_mma<<<dim3(Ss/FQT, Bb*NHh), 256, FSMEM>>>();
    // 7) out = attn @ Wo
    mma_gemm<<<dim3(2048/128, NTOK/128), 256, GS_SMEM>>>(p_attn_h, p_attn_l, p_WoT_h, p_WoT_l, out, NTOK, 2048, HIDc);
}